// round 1
// baseline (speedup 1.0000x reference)
#include <cuda_runtime.h>
#include <math.h>

#define NSIG 5
#define NROWS 10
#define SIG_LEN 2097152
#define HALF 5
#define THREADS 256
#define EPT 8
#define TILE (THREADS*EPT)        /* 2048 */
#define CHUNKS (SIG_LEN/TILE)     /* 1024 */

struct __align__(16) P1Rec { float s; float ps; int c; int pad; };
struct __align__(16) ChunkRec { int first; int last; float inv; int pairs; };

__device__ P1Rec d_p1[NROWS*CHUNKS];
__device__ float d_thr[NROWS];
__device__ ChunkRec d_rec[NROWS*CHUNKS];

static __device__ __forceinline__ float neg_inf() { return __int_as_float(0xff800000); }

__device__ __forceinline__ const float* row_ptr(const float* rppg, const float* ppg, int s){
  return (s < NSIG) ? rppg + (size_t)s*SIG_LEN : ppg + (size_t)(s-NSIG)*SIG_LEN;
}

// Load v[0..17] = x[p0-5 .. p0+12] (thread owns outputs p0..p0+7).
// Main 8 via 2x float4; +/-5 halo via warp shuffles; warp-edge lanes read global.
__device__ __forceinline__ void load_vals(const float* __restrict__ x, int p0, float* v){
  float4 a = *reinterpret_cast<const float4*>(x + p0);
  float4 b = *reinterpret_cast<const float4*>(x + p0 + 4);
  v[5]=a.x; v[6]=a.y; v[7]=a.z; v[8]=a.w;
  v[9]=b.x; v[10]=b.y; v[11]=b.z; v[12]=b.w;
  const unsigned FULL = 0xFFFFFFFFu;
  v[0]  = __shfl_up_sync(FULL, v[8], 1);
  v[1]  = __shfl_up_sync(FULL, v[9], 1);
  v[2]  = __shfl_up_sync(FULL, v[10], 1);
  v[3]  = __shfl_up_sync(FULL, v[11], 1);
  v[4]  = __shfl_up_sync(FULL, v[12], 1);
  v[13] = __shfl_down_sync(FULL, v[5], 1);
  v[14] = __shfl_down_sync(FULL, v[6], 1);
  v[15] = __shfl_down_sync(FULL, v[7], 1);
  v[16] = __shfl_down_sync(FULL, v[8], 1);
  v[17] = __shfl_down_sync(FULL, v[9], 1);
  int lane = threadIdx.x & 31;
  if (lane == 0) {
    #pragma unroll
    for (int k = 0; k < HALF; k++) {
      int g = p0 - HALF + k;
      v[k] = (g >= 0) ? __ldg(x + g) : neg_inf();
    }
  }
  if (lane == 31) {
    #pragma unroll
    for (int k = 0; k < HALF; k++) {
      int g = p0 + EPT + k;
      v[13+k] = (g < SIG_LEN) ? __ldg(x + g) : neg_inf();
    }
  }
}

// Centered width-11 sliding max for the 8 owned outputs, register max-tree.
__device__ __forceinline__ void window_max(const float* v, float* w){
  float a2[17];
  #pragma unroll
  for (int i = 0; i < 17; i++) a2[i] = fmaxf(v[i], v[i+1]);
  float a4[15];
  #pragma unroll
  for (int i = 0; i < 15; i++) a4[i] = fmaxf(a2[i], a2[i+2]);
  float a8[11];
  #pragma unroll
  for (int i = 0; i < 11; i++) a8[i] = fmaxf(a4[i], a4[i+4]);
  #pragma unroll
  for (int i = 0; i < EPT; i++) w[i] = fmaxf(a8[i], a8[i+3]);  // covers v[i..i+10]
}

// Pass 1: per-chunk sum(x), peak count, peak value sum (raw data — affine-invariant mask).
__global__ void __launch_bounds__(THREADS) k_pass1(const float* __restrict__ rppg,
                                                   const float* __restrict__ ppg){
  int s = blockIdx.y;
  const float* __restrict__ x = row_ptr(rppg, ppg, s);
  int p0 = blockIdx.x * TILE + threadIdx.x * EPT;
  float v[18]; load_vals(x, p0, v);
  float w[EPT]; window_max(v, w);
  float lsum = 0.f, lps = 0.f; int lc = 0;
  #pragma unroll
  for (int i = 0; i < EPT; i++) {
    float c = v[i + HALF];
    lsum += c;
    if (c == w[i]) { lps += c; lc++; }
  }
  __shared__ float rA[THREADS]; __shared__ float rB[THREADS]; __shared__ int rC[THREADS];
  int tid = threadIdx.x;
  rA[tid] = lsum; rB[tid] = lps; rC[tid] = lc;
  __syncthreads();
  #pragma unroll
  for (int off = THREADS/2; off > 0; off >>= 1) {
    if (tid < off) { rA[tid] += rA[tid+off]; rB[tid] += rB[tid+off]; rC[tid] += rC[tid+off]; }
    __syncthreads();
  }
  if (tid == 0) {
    P1Rec r; r.s = rA[0]; r.ps = rB[0]; r.c = rC[0]; r.pad = 0;
    d_p1[s*CHUNKS + blockIdx.x] = r;
  }
}

// Deterministic per-row reduction of pass-1 partials -> threshold (mean_pk_raw + mu)/2.
__global__ void __launch_bounds__(THREADS) k_thr(){
  int s = blockIdx.x; int tid = threadIdx.x;
  double ls = 0.0, lps = 0.0; long long lc = 0;
  for (int c = tid; c < CHUNKS; c += THREADS) {
    P1Rec r = d_p1[s*CHUNKS + c];
    ls += (double)r.s; lps += (double)r.ps; lc += r.c;
  }
  __shared__ double sA[THREADS]; __shared__ double sB[THREADS]; __shared__ long long sC[THREADS];
  sA[tid] = ls; sB[tid] = lps; sC[tid] = lc;
  __syncthreads();
  #pragma unroll
  for (int off = THREADS/2; off > 0; off >>= 1) {
    if (tid < off) { sA[tid] += sA[tid+off]; sB[tid] += sB[tid+off]; sC[tid] += sC[tid+off]; }
    __syncthreads();
  }
  if (tid == 0) {
    double mu = sA[0] / (double)SIG_LEN;
    double mp = sB[0] / (double)sC[0];
    d_thr[s] = (float)(0.5 * (mp + mu));
  }
}

// Pass 2: filtered-peak gap sums per chunk (intra-thread sequential, cross-thread max-scan).
__global__ void __launch_bounds__(THREADS) k_pass2(const float* __restrict__ rppg,
                                                   const float* __restrict__ ppg){
  int s = blockIdx.y;
  const float* __restrict__ x = row_ptr(rppg, ppg, s);
  int p0 = blockIdx.x * TILE + threadIdx.x * EPT;
  float thr = d_thr[s];
  float v[18]; load_vals(x, p0, v);
  float w[EPT]; window_max(v, w);
  int lfirst = -1, lprev = -1, lpairs = 0; float linv = 0.f;
  #pragma unroll
  for (int i = 0; i < EPT; i++) {
    float c = v[i + HALF];
    if (c == w[i] && c > thr) {
      int g = p0 + i;
      if (lprev >= 0) { linv += 1.0f / (float)(g - lprev); lpairs++; }
      else lfirst = g;
      lprev = g;
    }
  }
  int tid = threadIdx.x;
  // inclusive max-scan of per-thread last-peak index
  __shared__ int sa[THREADS];
  sa[tid] = lprev;
  __syncthreads();
  #pragma unroll
  for (int off = 1; off < THREADS; off <<= 1) {
    int o = (tid >= off) ? sa[tid - off] : -1;
    __syncthreads();
    if (o > sa[tid]) sa[tid] = o;
    __syncthreads();
  }
  int exprev = (tid > 0) ? sa[tid-1] : -1;
  int blast = sa[THREADS-1];
  if (lfirst >= 0 && exprev >= 0) { linv += 1.0f / (float)(lfirst - exprev); lpairs++; }
  __shared__ float rF[THREADS]; __shared__ int rP[THREADS]; __shared__ int rM[THREADS];
  rF[tid] = linv; rP[tid] = lpairs; rM[tid] = (lfirst >= 0) ? lfirst : 0x7fffffff;
  __syncthreads();
  #pragma unroll
  for (int off = THREADS/2; off > 0; off >>= 1) {
    if (tid < off) {
      rF[tid] += rF[tid+off];
      rP[tid] += rP[tid+off];
      rM[tid] = min(rM[tid], rM[tid+off]);
    }
    __syncthreads();
  }
  if (tid == 0) {
    ChunkRec r;
    r.first = (rM[0] == 0x7fffffff) ? -1 : rM[0];
    r.last  = blast;
    r.inv   = rF[0];
    r.pairs = rP[0];
    d_rec[s*CHUNKS + blockIdx.x] = r;
  }
}

// Stitch chunks per row; combine to the scalar loss. (60*fs cancels in the ratio.)
__global__ void k_final(float* __restrict__ out){
  __shared__ double hrq[NROWS];
  int t = threadIdx.x;
  if (t < NROWS) {
    double inv = 0.0; long long pairs = 0; int prev = -1;
    const int4* rec = reinterpret_cast<const int4*>(d_rec) + (size_t)t * CHUNKS;
    for (int c = 0; c < CHUNKS; c++) {
      int4 rv = rec[c];
      if (rv.x >= 0) {
        if (prev >= 0) { inv += 1.0 / (double)(rv.x - prev); pairs++; }
        prev = rv.y;
      }
      inv += (double)__int_as_float(rv.z);
      pairs += rv.w;
    }
    hrq[t] = inv / (double)pairs;   // hr up to the common 60*fs factor
  }
  __syncthreads();
  if (t == 0) {
    double acc = 0.0;
    for (int i = 0; i < NSIG; i++) {
      double hp = hrq[NSIG + i];   // ppg row
      double hq = hrq[i];          // rppg row
      acc += fabs(hp - hq) / hp;
    }
    out[0] = (float)(acc / (double)NSIG);
  }
}

extern "C" void kernel_launch(void* const* d_in, const int* in_sizes, int n_in,
                              void* d_out, int out_size){
  (void)in_sizes; (void)n_in; (void)out_size;
  const float* rppg = (const float*)d_in[0];
  const float* ppg  = (const float*)d_in[1];
  float* out = (float*)d_out;
  dim3 grid(CHUNKS, NROWS);
  k_pass1<<<grid, THREADS>>>(rppg, ppg);
  k_thr<<<NROWS, THREADS>>>();
  k_pass2<<<grid, THREADS>>>(rppg, ppg);
  k_final<<<1, 32>>>(out);
}

// round 2
// speedup vs baseline: 6.4912x; 6.4912x over previous
#include <cuda_runtime.h>
#include <math.h>

#define NSIG 5
#define NROWS 10
#define SIG_LEN 2097152
#define HALF 5
#define THREADS 256
#define EPT 8
#define TILE (THREADS*EPT)        /* 2048 */
#define CHUNKS (SIG_LEN/TILE)     /* 1024 */
#define RPT (CHUNKS/THREADS)      /* 4 records per thread in stitch */

struct __align__(16) P1Rec { float s; float ps; int c; int pad; };
struct __align__(16) ChunkRec { int first; int last; float inv; int pairs; };

__device__ P1Rec d_p1[NROWS*CHUNKS];
__device__ float d_thr[NROWS];
__device__ ChunkRec d_rec[NROWS*CHUNKS];
__device__ double d_hr[NROWS];

static __device__ __forceinline__ float neg_inf() { return __int_as_float(0xff800000); }

__device__ __forceinline__ const float* row_ptr(const float* rppg, const float* ppg, int s){
  return (s < NSIG) ? rppg + (size_t)s*SIG_LEN : ppg + (size_t)(s-NSIG)*SIG_LEN;
}

// Load v[0..17] = x[p0-5 .. p0+12] (thread owns outputs p0..p0+7).
// Main 8 via 2x float4; +/-5 halo via warp shuffles; warp-edge lanes read global.
__device__ __forceinline__ void load_vals(const float* __restrict__ x, int p0, float* v){
  float4 a = *reinterpret_cast<const float4*>(x + p0);
  float4 b = *reinterpret_cast<const float4*>(x + p0 + 4);
  v[5]=a.x; v[6]=a.y; v[7]=a.z; v[8]=a.w;
  v[9]=b.x; v[10]=b.y; v[11]=b.z; v[12]=b.w;
  const unsigned FULL = 0xFFFFFFFFu;
  v[0]  = __shfl_up_sync(FULL, v[8], 1);
  v[1]  = __shfl_up_sync(FULL, v[9], 1);
  v[2]  = __shfl_up_sync(FULL, v[10], 1);
  v[3]  = __shfl_up_sync(FULL, v[11], 1);
  v[4]  = __shfl_up_sync(FULL, v[12], 1);
  v[13] = __shfl_down_sync(FULL, v[5], 1);
  v[14] = __shfl_down_sync(FULL, v[6], 1);
  v[15] = __shfl_down_sync(FULL, v[7], 1);
  v[16] = __shfl_down_sync(FULL, v[8], 1);
  v[17] = __shfl_down_sync(FULL, v[9], 1);
  int lane = threadIdx.x & 31;
  if (lane == 0) {
    #pragma unroll
    for (int k = 0; k < HALF; k++) {
      int g = p0 - HALF + k;
      v[k] = (g >= 0) ? __ldg(x + g) : neg_inf();
    }
  }
  if (lane == 31) {
    #pragma unroll
    for (int k = 0; k < HALF; k++) {
      int g = p0 + EPT + k;
      v[13+k] = (g < SIG_LEN) ? __ldg(x + g) : neg_inf();
    }
  }
}

// Centered width-11 sliding max for the 8 owned outputs, register max-tree.
__device__ __forceinline__ void window_max(const float* v, float* w){
  float a2[17];
  #pragma unroll
  for (int i = 0; i < 17; i++) a2[i] = fmaxf(v[i], v[i+1]);
  float a4[15];
  #pragma unroll
  for (int i = 0; i < 15; i++) a4[i] = fmaxf(a2[i], a2[i+2]);
  float a8[11];
  #pragma unroll
  for (int i = 0; i < 11; i++) a8[i] = fmaxf(a4[i], a4[i+4]);
  #pragma unroll
  for (int i = 0; i < EPT; i++) w[i] = fmaxf(a8[i], a8[i+3]);  // covers v[i..i+10]
}

// Pass 1: per-chunk sum(x), peak count, peak value sum (raw data — affine-invariant mask).
__global__ void __launch_bounds__(THREADS) k_pass1(const float* __restrict__ rppg,
                                                   const float* __restrict__ ppg){
  int s = blockIdx.y;
  const float* __restrict__ x = row_ptr(rppg, ppg, s);
  int p0 = blockIdx.x * TILE + threadIdx.x * EPT;
  float v[18]; load_vals(x, p0, v);
  float w[EPT]; window_max(v, w);
  float lsum = 0.f, lps = 0.f; int lc = 0;
  #pragma unroll
  for (int i = 0; i < EPT; i++) {
    float c = v[i + HALF];
    lsum += c;
    if (c == w[i]) { lps += c; lc++; }
  }
  __shared__ float rA[THREADS]; __shared__ float rB[THREADS]; __shared__ int rC[THREADS];
  int tid = threadIdx.x;
  rA[tid] = lsum; rB[tid] = lps; rC[tid] = lc;
  __syncthreads();
  #pragma unroll
  for (int off = THREADS/2; off > 0; off >>= 1) {
    if (tid < off) { rA[tid] += rA[tid+off]; rB[tid] += rB[tid+off]; rC[tid] += rC[tid+off]; }
    __syncthreads();
  }
  if (tid == 0) {
    P1Rec r; r.s = rA[0]; r.ps = rB[0]; r.c = rC[0]; r.pad = 0;
    d_p1[s*CHUNKS + blockIdx.x] = r;
  }
}

// Deterministic per-row reduction of pass-1 partials -> threshold (mean_pk_raw + mu)/2.
__global__ void __launch_bounds__(THREADS) k_thr(){
  int s = blockIdx.x; int tid = threadIdx.x;
  double ls = 0.0, lps = 0.0; long long lc = 0;
  for (int c = tid; c < CHUNKS; c += THREADS) {
    P1Rec r = d_p1[s*CHUNKS + c];
    ls += (double)r.s; lps += (double)r.ps; lc += r.c;
  }
  __shared__ double sA[THREADS]; __shared__ double sB[THREADS]; __shared__ long long sC[THREADS];
  sA[tid] = ls; sB[tid] = lps; sC[tid] = lc;
  __syncthreads();
  #pragma unroll
  for (int off = THREADS/2; off > 0; off >>= 1) {
    if (tid < off) { sA[tid] += sA[tid+off]; sB[tid] += sB[tid+off]; sC[tid] += sC[tid+off]; }
    __syncthreads();
  }
  if (tid == 0) {
    double mu = sA[0] / (double)SIG_LEN;
    double mp = sB[0] / (double)sC[0];
    d_thr[s] = (float)(0.5 * (mp + mu));
  }
}

// Pass 2: filtered-peak gap sums per chunk (intra-thread sequential, cross-thread max-scan).
__global__ void __launch_bounds__(THREADS) k_pass2(const float* __restrict__ rppg,
                                                   const float* __restrict__ ppg){
  int s = blockIdx.y;
  const float* __restrict__ x = row_ptr(rppg, ppg, s);
  int p0 = blockIdx.x * TILE + threadIdx.x * EPT;
  float thr = d_thr[s];
  float v[18]; load_vals(x, p0, v);
  float w[EPT]; window_max(v, w);
  int lfirst = -1, lprev = -1, lpairs = 0; float linv = 0.f;
  #pragma unroll
  for (int i = 0; i < EPT; i++) {
    float c = v[i + HALF];
    if (c == w[i] && c > thr) {
      int g = p0 + i;
      if (lprev >= 0) { linv += 1.0f / (float)(g - lprev); lpairs++; }
      else lfirst = g;
      lprev = g;
    }
  }
  int tid = threadIdx.x;
  // inclusive max-scan of per-thread last-peak index
  __shared__ int sa[THREADS];
  sa[tid] = lprev;
  __syncthreads();
  #pragma unroll
  for (int off = 1; off < THREADS; off <<= 1) {
    int o = (tid >= off) ? sa[tid - off] : -1;
    __syncthreads();
    if (o > sa[tid]) sa[tid] = o;
    __syncthreads();
  }
  int exprev = (tid > 0) ? sa[tid-1] : -1;
  int blast = sa[THREADS-1];
  if (lfirst >= 0 && exprev >= 0) { linv += 1.0f / (float)(lfirst - exprev); lpairs++; }
  __shared__ float rF[THREADS]; __shared__ int rP[THREADS]; __shared__ int rM[THREADS];
  rF[tid] = linv; rP[tid] = lpairs; rM[tid] = (lfirst >= 0) ? lfirst : 0x7fffffff;
  __syncthreads();
  #pragma unroll
  for (int off = THREADS/2; off > 0; off >>= 1) {
    if (tid < off) {
      rF[tid] += rF[tid+off];
      rP[tid] += rP[tid+off];
      rM[tid] = min(rM[tid], rM[tid+off]);
    }
    __syncthreads();
  }
  if (tid == 0) {
    ChunkRec r;
    r.first = (rM[0] == 0x7fffffff) ? -1 : rM[0];
    r.last  = blast;
    r.inv   = rF[0];
    r.pairs = rP[0];
    d_rec[s*CHUNKS + blockIdx.x] = r;
  }
}

// Parallel per-row stitch: one 256-thread block per row, 4 records/thread.
// Same intra-thread-sequential + cross-thread max-scan pattern as k_pass2.
__global__ void __launch_bounds__(THREADS) k_stitch(){
  int s = blockIdx.x; int tid = threadIdx.x;
  const int4* rec = reinterpret_cast<const int4*>(d_rec) + (size_t)s * CHUNKS + (size_t)tid * RPT;
  double linv = 0.0; int lpairs = 0; int lfirst = -1, lprev = -1;
  #pragma unroll
  for (int r = 0; r < RPT; r++) {
    int4 rv = rec[r];
    if (rv.x >= 0) {                         // chunk has at least one peak
      if (lprev >= 0) { linv += 1.0 / (double)(rv.x - lprev); lpairs++; }
      else lfirst = rv.x;
      lprev = rv.y;
    }
    linv += (double)__int_as_float(rv.z);
    lpairs += rv.w;
  }
  // cross-thread max-scan of last-peak index (indices increase with tid)
  __shared__ int sa[THREADS];
  sa[tid] = lprev;
  __syncthreads();
  #pragma unroll
  for (int off = 1; off < THREADS; off <<= 1) {
    int o = (tid >= off) ? sa[tid - off] : -1;
    __syncthreads();
    if (o > sa[tid]) sa[tid] = o;
    __syncthreads();
  }
  int exprev = (tid > 0) ? sa[tid-1] : -1;
  if (lfirst >= 0 && exprev >= 0) { linv += 1.0 / (double)(lfirst - exprev); lpairs++; }
  __shared__ double rF[THREADS]; __shared__ int rP[THREADS];
  rF[tid] = linv; rP[tid] = lpairs;
  __syncthreads();
  #pragma unroll
  for (int off = THREADS/2; off > 0; off >>= 1) {
    if (tid < off) { rF[tid] += rF[tid+off]; rP[tid] += rP[tid+off]; }
    __syncthreads();
  }
  if (tid == 0) d_hr[s] = rF[0] / (double)rP[0];  // hr up to common 60*fs factor
}

// Combine 10 per-row hr values into the scalar loss. (60*fs cancels in the ratio.)
__global__ void k_final(float* __restrict__ out){
  if (threadIdx.x == 0) {
    double acc = 0.0;
    #pragma unroll
    for (int i = 0; i < NSIG; i++) {
      double hp = d_hr[NSIG + i];   // ppg row
      double hq = d_hr[i];          // rppg row
      acc += fabs(hp - hq) / hp;
    }
    out[0] = (float)(acc / (double)NSIG);
  }
}

extern "C" void kernel_launch(void* const* d_in, const int* in_sizes, int n_in,
                              void* d_out, int out_size){
  (void)in_sizes; (void)n_in; (void)out_size;
  const float* rppg = (const float*)d_in[0];
  const float* ppg  = (const float*)d_in[1];
  float* out = (float*)d_out;
  dim3 grid(CHUNKS, NROWS);
  k_pass1<<<grid, THREADS>>>(rppg, ppg);
  k_thr<<<NROWS, THREADS>>>();
  k_pass2<<<grid, THREADS>>>(rppg, ppg);
  k_stitch<<<NROWS, THREADS>>>();
  k_final<<<1, 32>>>(out);
}

// round 3
// speedup vs baseline: 7.2538x; 1.1175x over previous
#include <cuda_runtime.h>
#include <math.h>
#include <limits.h>

#define NSIG 5
#define NROWS 10
#define SIG_LEN 2097152
#define HALF 5
#define THREADS 256
#define EPT 8
#define TILE (THREADS*EPT)        /* 2048 */
#define CHUNKS (SIG_LEN/TILE)     /* 1024 */
#define RPT (CHUNKS/THREADS)      /* 4 records per thread in stitch */
#define CAP 384                   /* peak slots per chunk (>= ceil(2048/6)) */
#define KPL (CAP/32)              /* 12 entries per lane in pass2 */
#define FULLM 0xFFFFFFFFu

struct __align__(16) P1Rec { float s; float ps; int c; int pad; };
struct __align__(16) ChunkRec { int first; int last; float inv; int pairs; };

__device__ P1Rec d_p1[NROWS*CHUNKS];
__device__ float d_thr[NROWS];
__device__ ChunkRec d_rec[NROWS*CHUNKS];
__device__ double d_hr[NROWS];
__device__ int2 d_pk[(size_t)NROWS*CHUNKS*CAP];   /* compact peak lists */
__device__ int d_cnt[NROWS*CHUNKS];

static __device__ __forceinline__ float neg_inf() { return __int_as_float(0xff800000); }

__device__ __forceinline__ const float* row_ptr(const float* rppg, const float* ppg, int s){
  return (s < NSIG) ? rppg + (size_t)s*SIG_LEN : ppg + (size_t)(s-NSIG)*SIG_LEN;
}

// Load v[0..17] = x[p0-5 .. p0+12] (thread owns outputs p0..p0+7).
__device__ __forceinline__ void load_vals(const float* __restrict__ x, int p0, float* v){
  float4 a = *reinterpret_cast<const float4*>(x + p0);
  float4 b = *reinterpret_cast<const float4*>(x + p0 + 4);
  v[5]=a.x; v[6]=a.y; v[7]=a.z; v[8]=a.w;
  v[9]=b.x; v[10]=b.y; v[11]=b.z; v[12]=b.w;
  v[0]  = __shfl_up_sync(FULLM, v[8], 1);
  v[1]  = __shfl_up_sync(FULLM, v[9], 1);
  v[2]  = __shfl_up_sync(FULLM, v[10], 1);
  v[3]  = __shfl_up_sync(FULLM, v[11], 1);
  v[4]  = __shfl_up_sync(FULLM, v[12], 1);
  v[13] = __shfl_down_sync(FULLM, v[5], 1);
  v[14] = __shfl_down_sync(FULLM, v[6], 1);
  v[15] = __shfl_down_sync(FULLM, v[7], 1);
  v[16] = __shfl_down_sync(FULLM, v[8], 1);
  v[17] = __shfl_down_sync(FULLM, v[9], 1);
  int lane = threadIdx.x & 31;
  if (lane == 0) {
    #pragma unroll
    for (int k = 0; k < HALF; k++) {
      int g = p0 - HALF + k;
      v[k] = (g >= 0) ? __ldg(x + g) : neg_inf();
    }
  }
  if (lane == 31) {
    #pragma unroll
    for (int k = 0; k < HALF; k++) {
      int g = p0 + EPT + k;
      v[13+k] = (g < SIG_LEN) ? __ldg(x + g) : neg_inf();
    }
  }
}

// Centered width-11 sliding max, register max-tree.
__device__ __forceinline__ void window_max(const float* v, float* w){
  float a2[17];
  #pragma unroll
  for (int i = 0; i < 17; i++) a2[i] = fmaxf(v[i], v[i+1]);
  float a4[15];
  #pragma unroll
  for (int i = 0; i < 15; i++) a4[i] = fmaxf(a2[i], a2[i+2]);
  float a8[11];
  #pragma unroll
  for (int i = 0; i < 11; i++) a8[i] = fmaxf(a4[i], a4[i+4]);
  #pragma unroll
  for (int i = 0; i < EPT; i++) w[i] = fmaxf(a8[i], a8[i+3]);
}

// Pass 1: per-chunk stats AND compact peak list (peak mask is thr-independent).
__global__ void __launch_bounds__(THREADS) k_pass1(const float* __restrict__ rppg,
                                                   const float* __restrict__ ppg){
  int s = blockIdx.y;
  const float* __restrict__ x = row_ptr(rppg, ppg, s);
  int tid = threadIdx.x, lane = tid & 31, wid = tid >> 5;
  int p0 = blockIdx.x * TILE + tid * EPT;
  float v[18]; load_vals(x, p0, v);
  float w[EPT]; window_max(v, w);
  float lsum = 0.f, lps = 0.f; int lc = 0;
  int ppos[4]; float pval[4]; int np = 0;   // min peak spacing 6 -> <=2 per 8 elems
  #pragma unroll
  for (int i = 0; i < EPT; i++) {
    float c = v[i + HALF];
    lsum += c;
    if (c == w[i]) {
      lps += c; lc++;
      if (np < 4) { ppos[np] = p0 + i; pval[np] = c; np++; }
    }
  }
  // block-wide exclusive prefix of np (warp shfl scan + cross-warp)
  int inc = np;
  #pragma unroll
  for (int off = 1; off < 32; off <<= 1) {
    int t = __shfl_up_sync(FULLM, inc, off);
    if (lane >= off) inc += t;
  }
  int exc = inc - np;
  __shared__ int wsum[8]; __shared__ int wbase[9];
  if (lane == 31) wsum[wid] = inc;
  __syncthreads();
  if (tid == 0) {
    int b = 0;
    #pragma unroll
    for (int ww = 0; ww < 8; ww++) { wbase[ww] = b; b += wsum[ww]; }
    wbase[8] = b;
  }
  __syncthreads();
  int base = wbase[wid] + exc;
  size_t cbase = (size_t)(s*CHUNKS + blockIdx.x) * CAP;
  for (int j = 0; j < np; j++) {
    int slot = base + j;
    if (slot < CAP) d_pk[cbase + slot] = make_int2(ppos[j], __float_as_int(pval[j]));
  }
  if (tid == 0) d_cnt[s*CHUNKS + blockIdx.x] = min(wbase[8], CAP);
  // stats: warp reduce then cross-warp
  #pragma unroll
  for (int off = 16; off > 0; off >>= 1) {
    lsum += __shfl_down_sync(FULLM, lsum, off);
    lps  += __shfl_down_sync(FULLM, lps, off);
    lc   += __shfl_down_sync(FULLM, lc, off);
  }
  __shared__ float sA[8]; __shared__ float sB[8]; __shared__ int sC[8];
  if (lane == 0) { sA[wid] = lsum; sB[wid] = lps; sC[wid] = lc; }
  __syncthreads();
  if (wid == 0 && lane < 8) {
    float a = sA[lane], b = sB[lane]; int c = sC[lane];
    #pragma unroll
    for (int off = 4; off > 0; off >>= 1) {
      a += __shfl_down_sync(0xFF, a, off);
      b += __shfl_down_sync(0xFF, b, off);
      c += __shfl_down_sync(0xFF, c, off);
    }
    if (lane == 0) {
      P1Rec r; r.s = a; r.ps = b; r.c = c; r.pad = 0;
      d_p1[s*CHUNKS + blockIdx.x] = r;
    }
  }
}

// Per-row reduction of pass-1 partials -> threshold (mean_pk_raw + mu)/2.
__global__ void __launch_bounds__(THREADS) k_thr(){
  int s = blockIdx.x; int tid = threadIdx.x, lane = tid & 31, wid = tid >> 5;
  double ls = 0.0, lps = 0.0; long long lc = 0;
  for (int c = tid; c < CHUNKS; c += THREADS) {
    P1Rec r = d_p1[s*CHUNKS + c];
    ls += (double)r.s; lps += (double)r.ps; lc += r.c;
  }
  #pragma unroll
  for (int off = 16; off > 0; off >>= 1) {
    ls  += __shfl_down_sync(FULLM, ls, off);
    lps += __shfl_down_sync(FULLM, lps, off);
    lc  += __shfl_down_sync(FULLM, lc, off);
  }
  __shared__ double sA[8]; __shared__ double sB[8]; __shared__ long long sC[8];
  if (lane == 0) { sA[wid] = ls; sB[wid] = lps; sC[wid] = lc; }
  __syncthreads();
  if (wid == 0 && lane < 8) {
    double a = sA[lane], b = sB[lane]; long long c = sC[lane];
    #pragma unroll
    for (int off = 4; off > 0; off >>= 1) {
      a += __shfl_down_sync(0xFF, a, off);
      b += __shfl_down_sync(0xFF, b, off);
      c += __shfl_down_sync(0xFF, c, off);
    }
    if (lane == 0) {
      double mu = a / (double)SIG_LEN;
      double mp = b / (double)c;
      d_thr[s] = (float)(0.5 * (mp + mu));
    }
  }
}

// Pass 2: one warp per chunk, reads only the compact peak list.
__global__ void __launch_bounds__(32) k_pass2(){
  int s = blockIdx.y, c = blockIdx.x;
  int lane = threadIdx.x;
  float thr = d_thr[s];
  int n = d_cnt[s*CHUNKS + c];
  const int2* __restrict__ pk = d_pk + (size_t)(s*CHUNKS + c) * CAP;
  int lfirst = -1, lprev = -1, lpairs = 0; float linv = 0.f;
  int e0 = lane * KPL;
  #pragma unroll
  for (int j = 0; j < KPL; j++) {
    int e = e0 + j;
    if (e < n) {
      int2 r = pk[e];
      float val = __int_as_float(r.y);
      if (val > thr) {
        if (lprev >= 0) { linv += 1.0f / (float)(r.x - lprev); lpairs++; }
        else lfirst = r.x;
        lprev = r.x;
      }
    }
  }
  // warp inclusive max-scan of lprev
  int inc = lprev;
  #pragma unroll
  for (int off = 1; off < 32; off <<= 1) {
    int t = __shfl_up_sync(FULLM, inc, off);
    if (lane >= off) inc = max(inc, t);
  }
  int exprev = __shfl_up_sync(FULLM, inc, 1);
  if (lane == 0) exprev = -1;
  int blast = __shfl_sync(FULLM, inc, 31);
  if (lfirst >= 0 && exprev >= 0) { linv += 1.0f / (float)(lfirst - exprev); lpairs++; }
  int firstv = (lfirst >= 0) ? lfirst : INT_MAX;
  #pragma unroll
  for (int off = 16; off > 0; off >>= 1) {
    linv   += __shfl_down_sync(FULLM, linv, off);
    lpairs += __shfl_down_sync(FULLM, lpairs, off);
    firstv  = min(firstv, __shfl_down_sync(FULLM, firstv, off));
  }
  if (lane == 0) {
    ChunkRec r;
    r.first = (firstv == INT_MAX) ? -1 : firstv;
    r.last  = blast;
    r.inv   = linv;
    r.pairs = lpairs;
    d_rec[s*CHUNKS + c] = r;
  }
}

// Parallel per-row stitch, shuffle-based scans (2 barriers total).
__global__ void __launch_bounds__(THREADS) k_stitch(){
  int s = blockIdx.x; int tid = threadIdx.x, lane = tid & 31, wid = tid >> 5;
  const int4* rec = reinterpret_cast<const int4*>(d_rec) + (size_t)s * CHUNKS + (size_t)tid * RPT;
  double linv = 0.0; int lpairs = 0; int lfirst = -1, lprev = -1;
  #pragma unroll
  for (int r = 0; r < RPT; r++) {
    int4 rv = rec[r];
    if (rv.x >= 0) {
      if (lprev >= 0) { linv += 1.0 / (double)(rv.x - lprev); lpairs++; }
      else lfirst = rv.x;
      lprev = rv.y;
    }
    linv += (double)__int_as_float(rv.z);
    lpairs += rv.w;
  }
  // warp inclusive max-scan of lprev
  int inc = lprev;
  #pragma unroll
  for (int off = 1; off < 32; off <<= 1) {
    int t = __shfl_up_sync(FULLM, inc, off);
    if (lane >= off) inc = max(inc, t);
  }
  int exprev_w = __shfl_up_sync(FULLM, inc, 1);
  if (lane == 0) exprev_w = -1;
  __shared__ int wmax[8];
  if (lane == 31) wmax[wid] = inc;
  __syncthreads();
  int wpre = -1;
  for (int ww = 0; ww < wid; ww++) wpre = max(wpre, wmax[ww]);
  int exprev = max(exprev_w, wpre);
  if (lfirst >= 0 && exprev >= 0) { linv += 1.0 / (double)(lfirst - exprev); lpairs++; }
  #pragma unroll
  for (int off = 16; off > 0; off >>= 1) {
    linv   += __shfl_down_sync(FULLM, linv, off);
    lpairs += __shfl_down_sync(FULLM, lpairs, off);
  }
  __shared__ double sD[8]; __shared__ int sP[8];
  if (lane == 0) { sD[wid] = linv; sP[wid] = lpairs; }
  __syncthreads();
  if (wid == 0 && lane < 8) {
    double d = sD[lane]; int p = sP[lane];
    #pragma unroll
    for (int off = 4; off > 0; off >>= 1) {
      d += __shfl_down_sync(0xFF, d, off);
      p += __shfl_down_sync(0xFF, p, off);
    }
    if (lane == 0) d_hr[s] = d / (double)p;   // hr up to common 60*fs factor
  }
}

// Combine 10 per-row hr values; 60*fs cancels in the ratio.
__global__ void k_final(float* __restrict__ out){
  if (threadIdx.x == 0) {
    double acc = 0.0;
    #pragma unroll
    for (int i = 0; i < NSIG; i++) {
      double hp = d_hr[NSIG + i];   // ppg
      double hq = d_hr[i];          // rppg
      acc += fabs(hp - hq) / hp;
    }
    out[0] = (float)(acc / (double)NSIG);
  }
}

extern "C" void kernel_launch(void* const* d_in, const int* in_sizes, int n_in,
                              void* d_out, int out_size){
  (void)in_sizes; (void)n_in; (void)out_size;
  const float* rppg = (const float*)d_in[0];
  const float* ppg  = (const float*)d_in[1];
  float* out = (float*)d_out;
  dim3 grid(CHUNKS, NROWS);
  k_pass1<<<grid, THREADS>>>(rppg, ppg);
  k_thr<<<NROWS, THREADS>>>();
  k_pass2<<<grid, 32>>>();
  k_stitch<<<NROWS, THREADS>>>();
  k_final<<<1, 32>>>(out);
}